// round 1
// baseline (speedup 1.0000x reference)
#include <cuda_runtime.h>
#include <math.h>
#include <stdint.h>

#define BATCH 8
#define HDIM 56
#define WDIM 56
#define DIMC 256
#define NHEAD 8
#define HEADD 32
#define NTOK 3136
#define LWIN 9
#define PLP 49
#define ASCALE 0.0625f

// ---------------- scratch (static device arrays; no allocs allowed) -------
__device__ float g_Wcat[256 * 1024];
__device__ float g_bcat[1024];
__device__ float g_q[BATCH * NHEAD * NTOK * HEADD];    // (B,NH,N,HD)
__device__ float g_kv[BATCH * NTOK * 2 * DIMC];        // (B,N,512)
__device__ float g_xsr[BATCH * NTOK * DIMC];           // gelu(x@Wsr+bsr)
__device__ float g_xp[BATCH * PLP * DIMC];             // pooled+LN
__device__ float g_kvp[BATCH * PLP * 2 * DIMC];        // pooled kv
__device__ float g_opre[BATCH * NTOK * DIMC];          // pre-projection out

// ---------------- weight packing ------------------------------------------
__global__ void pack_w(const float* __restrict__ Wq, const float* __restrict__ bq,
                       const float* __restrict__ Wkv, const float* __restrict__ bkv,
                       const float* __restrict__ Wsr, const float* __restrict__ bsr) {
    int t = blockIdx.x * blockDim.x + threadIdx.x;
    if (t < 1024) {
        g_bcat[t] = (t < 256) ? bq[t] : (t < 768 ? bkv[t - 256] : bsr[t - 768]);
    }
    int stride = gridDim.x * blockDim.x;
    for (int idx = t; idx < 256 * 1024; idx += stride) {
        int k = idx >> 10, c = idx & 1023;
        float v;
        if (c < 256)      v = Wq[k * 256 + c];
        else if (c < 768) v = Wkv[k * 512 + (c - 256)];
        else              v = Wsr[k * 256 + (c - 768)];
        g_Wcat[idx] = v;
    }
}

// ---------------- tiled fp32 SGEMM, 128x128 block, 8x8/thread -------------
// mode 0: fused epilogue (q / kv / gelu-xsr), C unused
// mode 1: C[row*N+col] = acc + bias[col]
__global__ __launch_bounds__(256)
void sgemm(const float* __restrict__ A, const float* __restrict__ B,
           const float* __restrict__ bias, float* __restrict__ C,
           int M, int N, int K, int mode, const float* __restrict__ qe) {
    __shared__ float As[8][128];
    __shared__ float Bs[8][128];
    const int bm = blockIdx.y * 128, bn = blockIdx.x * 128;
    const int t = threadIdx.x;
    const int arow = t >> 1, acol4 = (t & 1) * 4;
    const int brow = t >> 5, bcol4 = (t & 31) * 4;
    const int tx = t & 15, ty = t >> 4;

    float acc[8][8];
#pragma unroll
    for (int i = 0; i < 8; i++)
#pragma unroll
        for (int j = 0; j < 8; j++) acc[i][j] = 0.f;

    for (int k0 = 0; k0 < K; k0 += 8) {
        float4 av = make_float4(0.f, 0.f, 0.f, 0.f);
        if (bm + arow < M)
            av = *(const float4*)(A + (size_t)(bm + arow) * K + k0 + acol4);
        As[acol4 + 0][arow] = av.x;
        As[acol4 + 1][arow] = av.y;
        As[acol4 + 2][arow] = av.z;
        As[acol4 + 3][arow] = av.w;
        float4 bv = *(const float4*)(B + (size_t)(k0 + brow) * N + bn + bcol4);
        *(float4*)(&Bs[brow][bcol4]) = bv;
        __syncthreads();
#pragma unroll
        for (int kk = 0; kk < 8; kk++) {
            float a[8], bb[8];
#pragma unroll
            for (int i = 0; i < 8; i++) a[i] = As[kk][ty * 8 + i];
#pragma unroll
            for (int j = 0; j < 8; j++) bb[j] = Bs[kk][tx * 8 + j];
#pragma unroll
            for (int i = 0; i < 8; i++)
#pragma unroll
                for (int j = 0; j < 8; j++) acc[i][j] = fmaf(a[i], bb[j], acc[i][j]);
        }
        __syncthreads();
    }

#pragma unroll
    for (int i = 0; i < 8; i++) {
        int row = bm + ty * 8 + i;
        if (row >= M) break;
        int b = row / NTOK, n = row % NTOK;  // used only in mode 0
#pragma unroll
        for (int j = 0; j < 8; j++) {
            int col = bn + tx * 8 + j;
            float v = acc[i][j] + bias[col];
            if (mode == 0) {
                if (col < 256) {
                    int h = col >> 5, d = col & 31;
                    v += qe[h * 32 + d];
                    g_q[(((size_t)b * NHEAD + h) * NTOK + n) * HEADD + d] = v;
                } else if (col < 768) {
                    g_kv[((size_t)b * NTOK + n) * 512 + (col - 256)] = v;
                } else {
                    float gl = 0.5f * v * (1.f + erff(v * 0.70710678118654752f));
                    g_xsr[((size_t)b * NTOK + n) * 256 + (col - 768)] = gl;
                }
            } else {
                C[(size_t)row * N + col] = v;
            }
        }
    }
}

// ---------------- pool (8x8 mean) + layernorm ------------------------------
__global__ void pool_ln(const float* __restrict__ ln_g, const float* __restrict__ ln_b) {
    int bp = blockIdx.x;             // b*49 + p
    int b = bp / PLP, p = bp % PLP;
    int ph = p / 7, pw = p % 7;
    int c = threadIdx.x;

    float s = 0.f;
    const float* base = g_xsr + (size_t)b * NTOK * 256 + c;
#pragma unroll
    for (int ii = 0; ii < 8; ii++)
#pragma unroll
        for (int jj = 0; jj < 8; jj++)
            s += base[(size_t)((ph * 8 + ii) * 56 + pw * 8 + jj) * 256];
    s *= (1.f / 64.f);

    __shared__ float red[256];
    red[c] = s;
    __syncthreads();
    for (int o = 128; o; o >>= 1) {
        if (c < o) red[c] += red[c + o];
        __syncthreads();
    }
    float mu = red[0] * (1.f / 256.f);
    __syncthreads();
    float d = s - mu;
    red[c] = d * d;
    __syncthreads();
    for (int o = 128; o; o >>= 1) {
        if (c < o) red[c] += red[c + o];
        __syncthreads();
    }
    float var = red[0] * (1.f / 256.f);
    float out = d * rsqrtf(var + 1e-5f) * ln_g[c] + ln_b[c];
    g_xp[(size_t)bp * 256 + c] = out;
}

// ---------------- attention -----------------------------------------------
__device__ __forceinline__ float wred(float v) {
#pragma unroll
    for (int o = 16; o; o >>= 1) v += __shfl_xor_sync(0xffffffffu, v, o);
    return v;
}

__global__ __launch_bounds__(256)
void attn(const float* __restrict__ pbp,   // (8,49)
          const float* __restrict__ pbl,   // (8,9)
          const float* __restrict__ LT,    // (8,32,9)
          const float* __restrict__ lb) {  // (8,1,9)
    __shared__ float sm[8][64];
    int bx = blockIdx.x;
    int b = bx / NTOK, n = bx % NTOK;
    int i = n / 56, j = n % 56;
    int h = threadIdx.x >> 5, lane = threadIdx.x & 31;

    float q = g_q[(((size_t)b * NHEAD + h) * NTOK + n) * HEADD + lane];
    const float* kvb = g_kv + (size_t)b * NTOK * 512;
    const float* kvpb = g_kvp + (size_t)b * PLP * 512;

    // local logits (masked -> -1e30)
#pragma unroll
    for (int l = 0; l < 9; l++) {
        int di = l / 3 - 1, dj = l % 3 - 1;
        int ii = i + di, jj = j + dj;
        bool ok = ((unsigned)ii < 56u) && ((unsigned)jj < 56u);
        float kval = ok ? kvb[(size_t)(ii * 56 + jj) * 512 + h * 32 + lane] : 0.f;
        float s = wred(q * kval);
        if (lane == 0) sm[h][l] = ok ? (s * ASCALE + pbl[h * 9 + l]) : -1e30f;
    }
    // pooled logits
    for (int p = 0; p < 49; p++) {
        float kval = kvpb[(size_t)p * 512 + h * 32 + lane];
        float s = wred(q * kval);
        if (lane == 0) sm[h][9 + p] = s * ASCALE + pbp[h * 49 + p];
    }
    __syncwarp();

    // softmax over 58 entries (each lane owns idx=lane and lane+32)
    float v0 = sm[h][lane];
    float v1 = (lane + 32 < 58) ? sm[h][lane + 32] : -1e30f;
    float mx = fmaxf(v0, v1);
#pragma unroll
    for (int o = 16; o; o >>= 1) mx = fmaxf(mx, __shfl_xor_sync(0xffffffffu, mx, o));
    float e0 = __expf(v0 - mx);
    float e1 = (lane + 32 < 58) ? __expf(v1 - mx) : 0.f;
    float ssum = wred(e0 + e1);
    float inv = 1.f / ssum;
    sm[h][lane] = e0 * inv;
    if (lane + 32 < 58) sm[h][lane + 32] = e1 * inv;
    __syncwarp();

    // A_l = q . LT[h,:,l] + lb[h,l] + a_loc_l   (overwrite local slots)
#pragma unroll
    for (int l = 0; l < 9; l++) {
        float lt = LT[(h * 32 + lane) * 9 + l];
        float s = wred(q * lt);
        if (lane == 0) sm[h][l] = s + lb[h * 9 + l] + sm[h][l];
    }
    __syncwarp();

    // output: sum_l A_l * v_loc + sum_p a_pool * v_pool  (masked l: v==0 -> skip)
    float acc = 0.f;
#pragma unroll
    for (int l = 0; l < 9; l++) {
        int di = l / 3 - 1, dj = l % 3 - 1;
        int ii = i + di, jj = j + dj;
        if (((unsigned)ii < 56u) && ((unsigned)jj < 56u)) {
            float vv = kvb[(size_t)(ii * 56 + jj) * 512 + 256 + h * 32 + lane];
            acc = fmaf(sm[h][l], vv, acc);
        }
    }
    for (int p = 0; p < 49; p++) {
        float vv = kvpb[(size_t)p * 512 + 256 + h * 32 + lane];
        acc = fmaf(sm[h][9 + p], vv, acc);
    }
    g_opre[((size_t)b * NTOK + n) * 256 + h * 32 + lane] = acc;
}

// ---------------- launch ----------------------------------------------------
extern "C" void kernel_launch(void* const* d_in, const int* in_sizes, int n_in,
                              void* d_out, int out_size) {
    (void)in_sizes; (void)n_in; (void)out_size;
    const float* x     = (const float*)d_in[0];
    const float* Wq    = (const float*)d_in[1];
    const float* bq    = (const float*)d_in[2];
    const float* Wkv   = (const float*)d_in[3];
    const float* bkv   = (const float*)d_in[4];
    const float* qe    = (const float*)d_in[5];
    const float* Wsr   = (const float*)d_in[6];
    const float* bsr   = (const float*)d_in[7];
    const float* ln_g  = (const float*)d_in[8];
    const float* ln_b  = (const float*)d_in[9];
    const float* pbp   = (const float*)d_in[10];
    const float* pbl   = (const float*)d_in[11];
    const float* LT    = (const float*)d_in[12];
    const float* lb    = (const float*)d_in[13];
    const float* Wproj = (const float*)d_in[14];
    const float* bproj = (const float*)d_in[15];
    float* out = (float*)d_out;

    float *pWcat, *pbcat, *pxp, *pkvp, *popre;
    cudaGetSymbolAddress((void**)&pWcat, g_Wcat);
    cudaGetSymbolAddress((void**)&pbcat, g_bcat);
    cudaGetSymbolAddress((void**)&pxp, g_xp);
    cudaGetSymbolAddress((void**)&pkvp, g_kvp);
    cudaGetSymbolAddress((void**)&popre, g_opre);

    pack_w<<<256, 256>>>(Wq, bq, Wkv, bkv, Wsr, bsr);

    // fused q/kv/xsr GEMM: (25088 x 1024 x 256)
    {
        dim3 grid(1024 / 128, (BATCH * NTOK) / 128);
        sgemm<<<grid, 256>>>(x, pWcat, pbcat, nullptr,
                             BATCH * NTOK, 1024, 256, 0, qe);
    }

    pool_ln<<<BATCH * PLP, 256>>>(ln_g, ln_b);

    // kvp GEMM: (392 x 512 x 256)
    {
        dim3 grid(512 / 128, (BATCH * PLP + 127) / 128);
        sgemm<<<grid, 256>>>(pxp, Wkv, bkv, pkvp,
                             BATCH * PLP, 512, 256, 1, nullptr);
    }

    attn<<<BATCH * NTOK, 256>>>(pbp, pbl, LT, lb);

    // projection GEMM: (25088 x 256 x 256) -> d_out
    {
        dim3 grid(256 / 128, (BATCH * NTOK) / 128);
        sgemm<<<grid, 256>>>(popre, Wproj, bproj, out,
                             BATCH * NTOK, 256, 256, 1, nullptr);
    }
}

// round 3
// speedup vs baseline: 1.4685x; 1.4685x over previous
#include <cuda_runtime.h>
#include <cuda_bf16.h>
#include <math.h>
#include <stdint.h>

#define BATCH 8
#define NTOK 3136
#define MROWS (BATCH * NTOK)   // 25088
#define ASCALE 0.0625f
#define PLP 49

// ---------------- scratch ---------------------------------------------------
__device__ __align__(128) float g_q[MROWS * 256];          // (B,NH,N,HD)
__device__ __align__(128) float g_kv[MROWS * 512];         // (B,N,512)
__device__ __align__(128) float g_xsr[MROWS * 256];
__device__ __align__(128) float g_xp[BATCH * PLP * 256];
__device__ __align__(128) float g_kvp[BATCH * PLP * 512];
__device__ __align__(128) float g_bcat[1024];
__device__ __align__(128) __nv_bfloat16 g_xhi[MROWS * 256];
__device__ __align__(128) __nv_bfloat16 g_xlo[MROWS * 256];
__device__ __align__(128) __nv_bfloat16 g_wthi[1024 * 256];   // W^T (N x K)
__device__ __align__(128) __nv_bfloat16 g_wtlo[1024 * 256];
__device__ __align__(128) __nv_bfloat16 g_wphi[256 * 256];    // Wproj^T
__device__ __align__(128) __nv_bfloat16 g_wplo[256 * 256];
__device__ __align__(128) __nv_bfloat16 g_ohi[MROWS * 256];
__device__ __align__(128) __nv_bfloat16 g_olo[MROWS * 256];

// ---------------- helpers ----------------------------------------------------
__device__ __forceinline__ uint32_t s2u(const void* p) {
    uint32_t a;
    asm("{ .reg .u64 t; cvta.to.shared.u64 t, %1; cvt.u32.u64 %0, t; }" : "=r"(a) : "l"(p));
    return a;
}
__device__ __forceinline__ void cp_async16(uint32_t saddr, const void* gaddr) {
    asm volatile("cp.async.cg.shared.global [%0], [%1], 16;" :: "r"(saddr), "l"(gaddr));
}
__device__ __forceinline__ void cp_commit() {
    asm volatile("cp.async.commit_group;");
}
__device__ __forceinline__ void ldsm4(uint32_t r[4], uint32_t addr) {
    asm volatile("ldmatrix.sync.aligned.m8n8.x4.shared.b16 {%0,%1,%2,%3}, [%4];"
                 : "=r"(r[0]), "=r"(r[1]), "=r"(r[2]), "=r"(r[3]) : "r"(addr));
}
__device__ __forceinline__ void hmma(float c[4], const uint32_t a[4],
                                     uint32_t b0, uint32_t b1) {
    asm volatile(
        "mma.sync.aligned.m16n8k16.row.col.f32.bf16.bf16.f32 "
        "{%0,%1,%2,%3}, {%4,%5,%6,%7}, {%8,%9}, {%0,%1,%2,%3};"
        : "+f"(c[0]), "+f"(c[1]), "+f"(c[2]), "+f"(c[3])
        : "r"(a[0]), "r"(a[1]), "r"(a[2]), "r"(a[3]), "r"(b0), "r"(b1));
}

// ---------------- weight packing + splitting --------------------------------
__global__ void pack_w(const float* __restrict__ Wq, const float* __restrict__ bq,
                       const float* __restrict__ Wkv, const float* __restrict__ bkv,
                       const float* __restrict__ Wsr, const float* __restrict__ bsr,
                       const float* __restrict__ qe, const float* __restrict__ Wproj) {
    int t = blockIdx.x * blockDim.x + threadIdx.x;
    int stride = gridDim.x * blockDim.x;
    if (t < 1024)
        g_bcat[t] = (t < 256) ? (bq[t] + qe[t]) : (t < 768 ? bkv[t - 256] : bsr[t - 768]);
    const int TOT = 1024 * 256 + 256 * 256;
    for (int idx = t; idx < TOT; idx += stride) {
        float w;
        if (idx < 1024 * 256) {
            int c = idx >> 8, k = idx & 255;
            if (c < 256)      w = Wq[k * 256 + c];
            else if (c < 768) w = Wkv[k * 512 + (c - 256)];
            else              w = Wsr[k * 256 + (c - 768)];
            __nv_bfloat16 h = __float2bfloat16(w);
            g_wthi[idx] = h;
            g_wtlo[idx] = __float2bfloat16(w - __bfloat162float(h));
        } else {
            int j = idx - 1024 * 256;
            int c = j >> 8, k = j & 255;
            w = Wproj[k * 256 + c];
            __nv_bfloat16 h = __float2bfloat16(w);
            g_wphi[j] = h;
            g_wplo[j] = __float2bfloat16(w - __bfloat162float(h));
        }
    }
}

__global__ void split_x(const float* __restrict__ x) {
    int i = blockIdx.x * blockDim.x + threadIdx.x;
    int stride = gridDim.x * blockDim.x;
    for (; i < MROWS * 256; i += stride) {
        float v = x[i];
        __nv_bfloat16 h = __float2bfloat16(v);
        g_xhi[i] = h;
        g_xlo[i] = __float2bfloat16(v - __bfloat162float(h));
    }
}

// ---------------- HMMA bf16x3 GEMM, 128x128 tile, K=256 ---------------------
// A: M x 256 row-major (hi/lo), B: N x 256 row-major (= W^T; hi/lo)
// mode 0: fused q/kv/xsr epilogue (N=1024); mode 1: C = acc + bias (N=256)
// smem per buffer: A tile 128 x 64 bf16 (stride 144B) = 18432B, B same.
#define SBUF 36864
__global__ __launch_bounds__(256, 2)
void gemm_mma(const __nv_bfloat16* __restrict__ Ah, const __nv_bfloat16* __restrict__ Al,
              const __nv_bfloat16* __restrict__ Bh, const __nv_bfloat16* __restrict__ Bl,
              const float* __restrict__ bias, float* __restrict__ Cout, int mode) {
    extern __shared__ __align__(128) uint8_t smem[];
    const int t = threadIdx.x, w = t >> 5, lane = t & 31;
    const int bm = blockIdx.y * 128, bn = blockIdx.x * 128;
    const int wm = (w >> 2) * 64, wn = (w & 3) * 32;
    const uint32_t sbase = s2u(smem);

    float c[4][4][4];
#pragma unroll
    for (int i = 0; i < 4; i++)
#pragma unroll
        for (int j = 0; j < 4; j++)
#pragma unroll
            for (int k = 0; k < 4; k++) c[i][j][k] = 0.f;

    // ldmatrix per-thread byte offsets within a buffer
    uint32_t aOff[4], bOff[2];
    {
        int r = lane & 15, kb = (lane >> 4) * 16;
#pragma unroll
        for (int mt = 0; mt < 4; mt++)
            aOff[mt] = (uint32_t)((wm + mt * 16 + r) * 144 + kb);
        int nr = wn + (lane >> 4) * 8 + (lane & 7);
        int kb2 = ((lane >> 3) & 1) * 16;
        bOff[0] = (uint32_t)(18432 + nr * 144 + kb2);
        bOff[1] = (uint32_t)(18432 + (nr + 16) * 144 + kb2);
    }
    const int s8 = t & 7;           // 16B segment within a 128B row
    const int rbase = t >> 3;       // row 0..31, +32*i

#define ISSUE(IT)                                                               \
    do {                                                                        \
        int _sgi = (IT) >> 2, _kc = (IT) & 3;                                   \
        const __nv_bfloat16* _Ap = (_sgi == 1) ? Al : Ah;                       \
        const __nv_bfloat16* _Bp = (_sgi == 2) ? Bl : Bh;                       \
        uint32_t _so = sbase + ((IT) & 1) * SBUF;                               \
        _Pragma("unroll")                                                       \
        for (int _i = 0; _i < 4; _i++) {                                        \
            int _r = rbase + _i * 32;                                           \
            cp_async16(_so + _r * 144 + s8 * 16,                                \
                       _Ap + (size_t)(bm + _r) * 256 + _kc * 64 + s8 * 8);      \
            cp_async16(_so + 18432 + _r * 144 + s8 * 16,                        \
                       _Bp + (size_t)(bn + _r) * 256 + _kc * 64 + s8 * 8);      \
        }                                                                       \
        cp_commit();                                                            \
    } while (0)

    ISSUE(0);
#pragma unroll 1
    for (int it = 0; it < 12; it++) {
        if (it < 11) {
            ISSUE(it + 1);
            asm volatile("cp.async.wait_group 1;");
        } else {
            asm volatile("cp.async.wait_group 0;");
        }
        __syncthreads();
        uint32_t so = sbase + (it & 1) * SBUF;
#pragma unroll
        for (int ks = 0; ks < 4; ks++) {
            uint32_t a[4][4], b[2][4];
#pragma unroll
            for (int mt = 0; mt < 4; mt++) ldsm4(a[mt], so + aOff[mt] + ks * 32);
#pragma unroll
            for (int np = 0; np < 2; np++) ldsm4(b[np], so + bOff[np] + ks * 32);
#pragma unroll
            for (int mt = 0; mt < 4; mt++)
#pragma unroll
                for (int nt = 0; nt < 4; nt++)
                    hmma(c[mt][nt], a[mt], b[nt >> 1][(nt & 1) * 2],
                         b[nt >> 1][(nt & 1) * 2 + 1]);
        }
        __syncthreads();
    }
#undef ISSUE

    // epilogue: c[mt][nt] = {(g, t2), (g, t2+1), (g+8, t2), (g+8, t2+1)}
    const int g = lane >> 2, tq = lane & 3;
#pragma unroll
    for (int mt = 0; mt < 4; mt++) {
#pragma unroll
        for (int rs = 0; rs < 2; rs++) {
            int row = bm + wm + mt * 16 + g + rs * 8;
            int b = row / NTOK, n = row - b * NTOK;
#pragma unroll
            for (int nt = 0; nt < 4; nt++) {
#pragma unroll
                for (int cs = 0; cs < 2; cs++) {
                    int col = bn + wn + nt * 8 + tq * 2 + cs;
                    float v = c[mt][nt][rs * 2 + cs] + bias[col];
                    if (mode == 0) {
                        if (col < 256) {
                            int h = col >> 5, d = col & 31;
                            g_q[(((size_t)b * 8 + h) * NTOK + n) * 32 + d] = v;
                        } else if (col < 768) {
                            g_kv[((size_t)b * NTOK + n) * 512 + (col - 256)] = v;
                        } else {
                            float gl = 0.5f * v * (1.f + erff(v * 0.70710678118654752f));
                            g_xsr[((size_t)b * NTOK + n) * 256 + (col - 768)] = gl;
                        }
                    } else {
                        Cout[(size_t)row * 256 + col] = v;
                    }
                }
            }
        }
    }
}

// ---------------- pool (8x8 mean) + layernorm --------------------------------
__global__ void pool_ln(const float* __restrict__ ln_g, const float* __restrict__ ln_b) {
    int bp = blockIdx.x;
    int b = bp / PLP, p = bp % PLP;
    int ph = p / 7, pw = p % 7;
    int c = threadIdx.x;
    float s = 0.f;
    const float* base = g_xsr + (size_t)b * NTOK * 256 + c;
#pragma unroll
    for (int ii = 0; ii < 8; ii++)
#pragma unroll
        for (int jj = 0; jj < 8; jj++)
            s += base[(size_t)((ph * 8 + ii) * 56 + pw * 8 + jj) * 256];
    s *= (1.f / 64.f);
    __shared__ float red[256];
    red[c] = s;
    __syncthreads();
    for (int o = 128; o; o >>= 1) { if (c < o) red[c] += red[c + o]; __syncthreads(); }
    float mu = red[0] * (1.f / 256.f);
    __syncthreads();
    float d = s - mu;
    red[c] = d * d;
    __syncthreads();
    for (int o = 128; o; o >>= 1) { if (c < o) red[c] += red[c + o]; __syncthreads(); }
    float var = red[0] * (1.f / 256.f);
    g_xp[(size_t)bp * 256 + c] = d * rsqrtf(var + 1e-5f) * ln_g[c] + ln_b[c];
}

// ---------------- small kvp GEMM (392 x 512 x 256) ---------------------------
__global__ __launch_bounds__(256)
void kvp_gemm(const float* __restrict__ Wkv, const float* __restrict__ bkv) {
    __shared__ float sx[2][256];
    int t = threadIdx.x;
    int r0 = blockIdx.x * 2;
    sx[0][t] = g_xp[(size_t)r0 * 256 + t];
    sx[1][t] = g_xp[(size_t)(r0 + 1) * 256 + t];
    __syncthreads();
    int c0 = t * 2;
    float a00 = 0.f, a01 = 0.f, a10 = 0.f, a11 = 0.f;
#pragma unroll 4
    for (int k = 0; k < 256; k++) {
        float2 w = *(const float2*)(Wkv + (size_t)k * 512 + c0);
        float x0 = sx[0][k], x1 = sx[1][k];
        a00 = fmaf(x0, w.x, a00);
        a01 = fmaf(x0, w.y, a01);
        a10 = fmaf(x1, w.x, a10);
        a11 = fmaf(x1, w.y, a11);
    }
    float b0 = bkv[c0], b1 = bkv[c0 + 1];
    g_kvp[(size_t)r0 * 512 + c0]           = a00 + b0;
    g_kvp[(size_t)r0 * 512 + c0 + 1]       = a01 + b1;
    g_kvp[(size_t)(r0 + 1) * 512 + c0]     = a10 + b0;
    g_kvp[(size_t)(r0 + 1) * 512 + c0 + 1] = a11 + b1;
}

// ---------------- attention ---------------------------------------------------
__device__ __forceinline__ float wred(float v) {
#pragma unroll
    for (int o = 16; o; o >>= 1) v += __shfl_xor_sync(0xffffffffu, v, o);
    return v;
}

__global__ __launch_bounds__(256)
void attn(const float* __restrict__ pbp, const float* __restrict__ pbl,
          const float* __restrict__ LT, const float* __restrict__ lb) {
    __shared__ float sm[8][64];
    int bx = blockIdx.x;
    int b = bx / NTOK, n = bx % NTOK;
    int i = n / 56, j = n % 56;
    int h = threadIdx.x >> 5, lane = threadIdx.x & 31;

    float q = g_q[(((size_t)b * 8 + h) * NTOK + n) * 32 + lane];
    const float* kvb = g_kv + (size_t)b * NTOK * 512;
    const float* kvpb = g_kvp + (size_t)b * PLP * 512;

#pragma unroll
    for (int l = 0; l < 9; l++) {
        int di = l / 3 - 1, dj = l % 3 - 1;
        int ii = i + di, jj = j + dj;
        bool ok = ((unsigned)ii < 56u) && ((unsigned)jj < 56u);
        float kval = ok ? kvb[(size_t)(ii * 56 + jj) * 512 + h * 32 + lane] : 0.f;
        float s = wred(q * kval);
        if (lane == 0) sm[h][l] = ok ? (s * ASCALE + pbl[h * 9 + l]) : -1e30f;
    }
    for (int p = 0; p < 49; p++) {
        float kval = kvpb[(size_t)p * 512 + h * 32 + lane];
        float s = wred(q * kval);
        if (lane == 0) sm[h][9 + p] = s * ASCALE + pbp[h * 49 + p];
    }
    __syncwarp();

    float v0 = sm[h][lane];
    float v1 = (lane + 32 < 58) ? sm[h][lane + 32] : -1e30f;
    float mx = fmaxf(v0, v1);
#pragma unroll
    for (int o = 16; o; o >>= 1) mx = fmaxf(mx, __shfl_xor_sync(0xffffffffu, mx, o));
    float e0 = __expf(v0 - mx);
    float e1 = (lane + 32 < 58) ? __expf(v1 - mx) : 0.f;
    float inv = 1.f / wred(e0 + e1);
    sm[h][lane] = e0 * inv;
    if (lane + 32 < 58) sm[h][lane + 32] = e1 * inv;
    __syncwarp();

#pragma unroll
    for (int l = 0; l < 9; l++) {
        float lt = LT[(h * 32 + lane) * 9 + l];
        float s = wred(q * lt);
        if (lane == 0) sm[h][l] = s + lb[h * 9 + l] + sm[h][l];
    }
    __syncwarp();

    float acc = 0.f;
#pragma unroll
    for (int l = 0; l < 9; l++) {
        int di = l / 3 - 1, dj = l % 3 - 1;
        int ii = i + di, jj = j + dj;
        if (((unsigned)ii < 56u) && ((unsigned)jj < 56u)) {
            float vv = kvb[(size_t)(ii * 56 + jj) * 512 + 256 + h * 32 + lane];
            acc = fmaf(sm[h][l], vv, acc);
        }
    }
    for (int p = 0; p < 49; p++) {
        float vv = kvpb[(size_t)p * 512 + 256 + h * 32 + lane];
        acc = fmaf(sm[h][9 + p], vv, acc);
    }
    size_t oidx = ((size_t)b * NTOK + n) * 256 + h * 32 + lane;
    __nv_bfloat16 hb = __float2bfloat16(acc);
    g_ohi[oidx] = hb;
    g_olo[oidx] = __float2bfloat16(acc - __bfloat162float(hb));
}

// ---------------- launch -------------------------------------------------------
extern "C" void kernel_launch(void* const* d_in, const int* in_sizes, int n_in,
                              void* d_out, int out_size) {
    (void)in_sizes; (void)n_in; (void)out_size;
    const float* x     = (const float*)d_in[0];
    const float* Wq    = (const float*)d_in[1];
    const float* bq    = (const float*)d_in[2];
    const float* Wkv   = (const float*)d_in[3];
    const float* bkv   = (const float*)d_in[4];
    const float* qe    = (const float*)d_in[5];
    const float* Wsr   = (const float*)d_in[6];
    const float* bsr   = (const float*)d_in[7];
    const float* ln_g  = (const float*)d_in[8];
    const float* ln_b  = (const float*)d_in[9];
    const float* pbp   = (const float*)d_in[10];
    const float* pbl   = (const float*)d_in[11];
    const float* LT    = (const float*)d_in[12];
    const float* lb    = (const float*)d_in[13];
    const float* Wproj = (const float*)d_in[14];
    const float* bproj = (const float*)d_in[15];
    float* out = (float*)d_out;

    __nv_bfloat16 *pxhi, *pxlo, *pwthi, *pwtlo, *pwphi, *pwplo, *pohi, *polo;
    float* pbcat;
    cudaGetSymbolAddress((void**)&pxhi, g_xhi);
    cudaGetSymbolAddress((void**)&pxlo, g_xlo);
    cudaGetSymbolAddress((void**)&pwthi, g_wthi);
    cudaGetSymbolAddress((void**)&pwtlo, g_wtlo);
    cudaGetSymbolAddress((void**)&pwphi, g_wphi);
    cudaGetSymbolAddress((void**)&pwplo, g_wplo);
    cudaGetSymbolAddress((void**)&pohi, g_ohi);
    cudaGetSymbolAddress((void**)&polo, g_olo);
    cudaGetSymbolAddress((void**)&pbcat, g_bcat);

    cudaFuncSetAttribute(gemm_mma, cudaFuncAttributeMaxDynamicSharedMemorySize, 2 * SBUF);

    pack_w<<<320, 256>>>(Wq, bq, Wkv, bkv, Wsr, bsr, qe, Wproj);
    split_x<<<2048, 256>>>(x);

    // fused q/kv/xsr GEMM: 25088 x 1024 x 256 (bf16x3 on HMMA)
    gemm_mma<<<dim3(8, 196), 256, 2 * SBUF>>>(pxhi, pxlo, pwthi, pwtlo, pbcat, nullptr, 0);

    pool_ln<<<BATCH * PLP, 256>>>(ln_g, ln_b);
    kvp_gemm<<<196, 256>>>(Wkv, bkv);
    attn<<<BATCH * NTOK, 256>>>(pbp, pbl, LT, lb);

    // projection GEMM: 25088 x 256 x 256 -> d_out
    gemm_mma<<<dim3(2, 196), 256, 2 * SBUF>>>(pohi, polo, pwphi, pwplo, bproj, out, 1);
}

// round 4
// speedup vs baseline: 2.8326x; 1.9290x over previous
#include <cuda_runtime.h>
#include <cuda_bf16.h>
#include <math.h>
#include <stdint.h>

#define BATCH 8
#define NTOK 3136
#define MROWS (BATCH * NTOK)   // 25088
#define ASCALE 0.0625f
#define PLP 49

// ---------------- scratch ---------------------------------------------------
__device__ __align__(128) float g_q[MROWS * 256];          // (B,NH,N,HD)
__device__ __align__(128) float g_kv[MROWS * 512];         // (B,N,512)
__device__ __align__(128) float g_xsr[MROWS * 256];
__device__ __align__(128) float g_xp[BATCH * PLP * 256];
__device__ __align__(128) float g_kvp[BATCH * PLP * 512];
__device__ __align__(128) float g_bcat[1024];
__device__ __align__(128) __nv_bfloat16 g_xhi[MROWS * 256];
__device__ __align__(128) __nv_bfloat16 g_xlo[MROWS * 256];
__device__ __align__(128) __nv_bfloat16 g_wthi[1024 * 256];   // W^T (N x K)
__device__ __align__(128) __nv_bfloat16 g_wtlo[1024 * 256];
__device__ __align__(128) __nv_bfloat16 g_wphi[256 * 256];    // Wproj^T
__device__ __align__(128) __nv_bfloat16 g_wplo[256 * 256];
__device__ __align__(128) __nv_bfloat16 g_ohi[MROWS * 256];
__device__ __align__(128) __nv_bfloat16 g_olo[MROWS * 256];

// ---------------- helpers ----------------------------------------------------
__device__ __forceinline__ uint32_t s2u(const void* p) {
    uint32_t a;
    asm("{ .reg .u64 t; cvta.to.shared.u64 t, %1; cvt.u32.u64 %0, t; }" : "=r"(a) : "l"(p));
    return a;
}
__device__ __forceinline__ void cp_async16(uint32_t saddr, const void* gaddr) {
    asm volatile("cp.async.cg.shared.global [%0], [%1], 16;" :: "r"(saddr), "l"(gaddr));
}
__device__ __forceinline__ void cp_commit() {
    asm volatile("cp.async.commit_group;");
}
__device__ __forceinline__ void ldsm4(uint32_t r[4], uint32_t addr) {
    asm volatile("ldmatrix.sync.aligned.m8n8.x4.shared.b16 {%0,%1,%2,%3}, [%4];"
                 : "=r"(r[0]), "=r"(r[1]), "=r"(r[2]), "=r"(r[3]) : "r"(addr));
}
__device__ __forceinline__ void hmma(float c[4], const uint32_t a[4],
                                     uint32_t b0, uint32_t b1) {
    asm volatile(
        "mma.sync.aligned.m16n8k16.row.col.f32.bf16.bf16.f32 "
        "{%0,%1,%2,%3}, {%4,%5,%6,%7}, {%8,%9}, {%0,%1,%2,%3};"
        : "+f"(c[0]), "+f"(c[1]), "+f"(c[2]), "+f"(c[3])
        : "r"(a[0]), "r"(a[1]), "r"(a[2]), "r"(a[3]), "r"(b0), "r"(b1));
}

// ---------------- weight packing + splitting --------------------------------
__global__ void pack_w(const float* __restrict__ Wq, const float* __restrict__ bq,
                       const float* __restrict__ Wkv, const float* __restrict__ bkv,
                       const float* __restrict__ Wsr, const float* __restrict__ bsr,
                       const float* __restrict__ qe, const float* __restrict__ Wproj) {
    int t = blockIdx.x * blockDim.x + threadIdx.x;
    int stride = gridDim.x * blockDim.x;
    if (t < 1024)
        g_bcat[t] = (t < 256) ? (bq[t] + qe[t]) : (t < 768 ? bkv[t - 256] : bsr[t - 768]);
    const int TOT = 1024 * 256 + 256 * 256;
    for (int idx = t; idx < TOT; idx += stride) {
        float w;
        if (idx < 1024 * 256) {
            int c = idx >> 8, k = idx & 255;
            if (c < 256)      w = Wq[k * 256 + c];
            else if (c < 768) w = Wkv[k * 512 + (c - 256)];
            else              w = Wsr[k * 256 + (c - 768)];
            __nv_bfloat16 h = __float2bfloat16(w);
            g_wthi[idx] = h;
            g_wtlo[idx] = __float2bfloat16(w - __bfloat162float(h));
        } else {
            int j = idx - 1024 * 256;
            int c = j >> 8, k = j & 255;
            w = Wproj[k * 256 + c];
            __nv_bfloat16 h = __float2bfloat16(w);
            g_wphi[j] = h;
            g_wplo[j] = __float2bfloat16(w - __bfloat162float(h));
        }
    }
}

__global__ void split_x(const float* __restrict__ x) {
    int i = blockIdx.x * blockDim.x + threadIdx.x;
    int stride = gridDim.x * blockDim.x;
    for (; i < MROWS * 256; i += stride) {
        float v = x[i];
        __nv_bfloat16 h = __float2bfloat16(v);
        g_xhi[i] = h;
        g_xlo[i] = __float2bfloat16(v - __bfloat162float(h));
    }
}

// ---------------- HMMA bf16x3 GEMM, 128x128 tile, K=256 ---------------------
#define SBUF 36864
__global__ __launch_bounds__(256, 2)
void gemm_mma(const __nv_bfloat16* __restrict__ Ah, const __nv_bfloat16* __restrict__ Al,
              const __nv_bfloat16* __restrict__ Bh, const __nv_bfloat16* __restrict__ Bl,
              const float* __restrict__ bias, float* __restrict__ Cout, int mode) {
    extern __shared__ __align__(128) uint8_t smem[];
    const int t = threadIdx.x, w = t >> 5, lane = t & 31;
    const int bm = blockIdx.y * 128, bn = blockIdx.x * 128;
    const int wm = (w >> 2) * 64, wn = (w & 3) * 32;
    const uint32_t sbase = s2u(smem);

    float c[4][4][4];
#pragma unroll
    for (int i = 0; i < 4; i++)
#pragma unroll
        for (int j = 0; j < 4; j++)
#pragma unroll
            for (int k = 0; k < 4; k++) c[i][j][k] = 0.f;

    uint32_t aOff[4], bOff[2];
    {
        int r = lane & 15, kb = (lane >> 4) * 16;
#pragma unroll
        for (int mt = 0; mt < 4; mt++)
            aOff[mt] = (uint32_t)((wm + mt * 16 + r) * 144 + kb);
        int nr = wn + (lane >> 4) * 8 + (lane & 7);
        int kb2 = ((lane >> 3) & 1) * 16;
        bOff[0] = (uint32_t)(18432 + nr * 144 + kb2);
        bOff[1] = (uint32_t)(18432 + (nr + 16) * 144 + kb2);
    }
    const int s8 = t & 7;
    const int rbase = t >> 3;

#define ISSUE(IT)                                                               \
    do {                                                                        \
        int _sgi = (IT) >> 2, _kc = (IT) & 3;                                   \
        const __nv_bfloat16* _Ap = (_sgi == 1) ? Al : Ah;                       \
        const __nv_bfloat16* _Bp = (_sgi == 2) ? Bl : Bh;                       \
        uint32_t _so = sbase + ((IT) & 1) * SBUF;                               \
        _Pragma("unroll")                                                       \
        for (int _i = 0; _i < 4; _i++) {                                        \
            int _r = rbase + _i * 32;                                           \
            cp_async16(_so + _r * 144 + s8 * 16,                                \
                       _Ap + (size_t)(bm + _r) * 256 + _kc * 64 + s8 * 8);      \
            cp_async16(_so + 18432 + _r * 144 + s8 * 16,                        \
                       _Bp + (size_t)(bn + _r) * 256 + _kc * 64 + s8 * 8);      \
        }                                                                       \
        cp_commit();                                                            \
    } while (0)

    ISSUE(0);
#pragma unroll 1
    for (int it = 0; it < 12; it++) {
        if (it < 11) {
            ISSUE(it + 1);
            asm volatile("cp.async.wait_group 1;");
        } else {
            asm volatile("cp.async.wait_group 0;");
        }
        __syncthreads();
        uint32_t so = sbase + (it & 1) * SBUF;
#pragma unroll
        for (int ks = 0; ks < 4; ks++) {
            uint32_t a[4][4], b[2][4];
#pragma unroll
            for (int mt = 0; mt < 4; mt++) ldsm4(a[mt], so + aOff[mt] + ks * 32);
#pragma unroll
            for (int np = 0; np < 2; np++) ldsm4(b[np], so + bOff[np] + ks * 32);
#pragma unroll
            for (int mt = 0; mt < 4; mt++)
#pragma unroll
                for (int nt = 0; nt < 4; nt++)
                    hmma(c[mt][nt], a[mt], b[nt >> 1][(nt & 1) * 2],
                         b[nt >> 1][(nt & 1) * 2 + 1]);
        }
        __syncthreads();
    }
#undef ISSUE

    const int g = lane >> 2, tq = lane & 3;
#pragma unroll
    for (int mt = 0; mt < 4; mt++) {
#pragma unroll
        for (int rs = 0; rs < 2; rs++) {
            int row = bm + wm + mt * 16 + g + rs * 8;
            int b = row / NTOK, n = row - b * NTOK;
#pragma unroll
            for (int nt = 0; nt < 4; nt++) {
#pragma unroll
                for (int cs = 0; cs < 2; cs++) {
                    int col = bn + wn + nt * 8 + tq * 2 + cs;
                    float v = c[mt][nt][rs * 2 + cs] + bias[col];
                    if (mode == 0) {
                        if (col < 256) {
                            int h = col >> 5, d = col & 31;
                            g_q[(((size_t)b * 8 + h) * NTOK + n) * 32 + d] = v;
                        } else if (col < 768) {
                            g_kv[((size_t)b * NTOK + n) * 512 + (col - 256)] = v;
                        } else {
                            float gl = 0.5f * v * (1.f + erff(v * 0.70710678118654752f));
                            g_xsr[((size_t)b * NTOK + n) * 256 + (col - 768)] = gl;
                        }
                    } else {
                        Cout[(size_t)row * 256 + col] = v;
                    }
                }
            }
        }
    }
}

// ---------------- pool (8x8 mean) + layernorm --------------------------------
__global__ void pool_ln(const float* __restrict__ ln_g, const float* __restrict__ ln_b) {
    int bp = blockIdx.x;
    int b = bp / PLP, p = bp % PLP;
    int ph = p / 7, pw = p % 7;
    int c = threadIdx.x;
    float s = 0.f;
    const float* base = g_xsr + (size_t)b * NTOK * 256 + c;
#pragma unroll
    for (int ii = 0; ii < 8; ii++)
#pragma unroll
        for (int jj = 0; jj < 8; jj++)
            s += base[(size_t)((ph * 8 + ii) * 56 + pw * 8 + jj) * 256];
    s *= (1.f / 64.f);
    __shared__ float red[256];
    red[c] = s;
    __syncthreads();
    for (int o = 128; o; o >>= 1) { if (c < o) red[c] += red[c + o]; __syncthreads(); }
    float mu = red[0] * (1.f / 256.f);
    __syncthreads();
    float d = s - mu;
    red[c] = d * d;
    __syncthreads();
    for (int o = 128; o; o >>= 1) { if (c < o) red[c] += red[c + o]; __syncthreads(); }
    float var = red[0] * (1.f / 256.f);
    g_xp[(size_t)bp * 256 + c] = d * rsqrtf(var + 1e-5f) * ln_g[c] + ln_b[c];
}

// ---------------- small kvp GEMM (392 x 512 x 256) ---------------------------
__global__ __launch_bounds__(256)
void kvp_gemm(const float* __restrict__ Wkv, const float* __restrict__ bkv) {
    __shared__ float sx[2][256];
    int t = threadIdx.x;
    int r0 = blockIdx.x * 2;
    sx[0][t] = g_xp[(size_t)r0 * 256 + t];
    sx[1][t] = g_xp[(size_t)(r0 + 1) * 256 + t];
    __syncthreads();
    int c0 = t * 2;
    float a00 = 0.f, a01 = 0.f, a10 = 0.f, a11 = 0.f;
#pragma unroll 4
    for (int k = 0; k < 256; k++) {
        float2 w = *(const float2*)(Wkv + (size_t)k * 512 + c0);
        float x0 = sx[0][k], x1 = sx[1][k];
        a00 = fmaf(x0, w.x, a00);
        a01 = fmaf(x0, w.y, a01);
        a10 = fmaf(x1, w.x, a10);
        a11 = fmaf(x1, w.y, a11);
    }
    float b0 = bkv[c0], b1 = bkv[c0 + 1];
    g_kvp[(size_t)r0 * 512 + c0]           = a00 + b0;
    g_kvp[(size_t)r0 * 512 + c0 + 1]       = a01 + b1;
    g_kvp[(size_t)(r0 + 1) * 512 + c0]     = a10 + b0;
    g_kvp[(size_t)(r0 + 1) * 512 + c0 + 1] = a11 + b1;
}

// ---------------- attention v2: lane = token, zero shuffles -------------------
// block = one (b,h) x 2 rows; 4 warps x 28 tokens.
// smem: sk[32][232], sv[32][232] (d-major, rows i0-1..i0+2, col slots -1..56),
//       skp[49][32], svp[49][32], sLT[9][32]
#define SK_OFF   0
#define SV_OFF   7424
#define SKP_OFF  14848
#define SVP_OFF  16416
#define SLT_OFF  17984
#define ATTN_SMEM_FLOATS 18272

__global__ __launch_bounds__(128, 3)
void attn2(const float* __restrict__ pbp, const float* __restrict__ pbl,
           const float* __restrict__ LT, const float* __restrict__ lb) {
    extern __shared__ __align__(16) float sm[];
    float* sk  = sm + SK_OFF;
    float* sv  = sm + SV_OFF;
    float* skp = sm + SKP_OFF;
    float* svp = sm + SVP_OFF;
    float* sLT = sm + SLT_OFF;

    const int t = threadIdx.x, w = t >> 5, lane = t & 31;
    const int rp = blockIdx.x;       // 0..27
    const int h  = blockIdx.y;       // 0..7
    const int b  = blockIdx.z;       // 0..7
    const int i0 = rp * 2;

    // ---- zero k/v staging (pads + OOB rows stay 0) ----
    {
        float4* z = (float4*)sm;
        for (int idx = t; idx < (2 * 32 * 232) / 4; idx += 128)
            z[idx] = make_float4(0.f, 0.f, 0.f, 0.f);
    }
    __syncthreads();

    // ---- stage local k/v rows i0-1..i0+2, d-major ----
    for (int tok = t; tok < 224; tok += 128) {
        int ri = tok / 56, cc = tok - ri * 56;
        int gr = i0 - 1 + ri;
        if ((unsigned)gr < 56u) {
            int n = gr * 56 + cc;
            const float4* kg = (const float4*)(g_kv + ((size_t)(b * NTOK + n) * 512 + h * 32));
            int sb = ri * 58 + cc + 1;
#pragma unroll
            for (int u = 0; u < 8; u++) {
                float4 kk = kg[u];
                float4 vv = kg[64 + u];
                sk[(u * 4 + 0) * 232 + sb] = kk.x;
                sk[(u * 4 + 1) * 232 + sb] = kk.y;
                sk[(u * 4 + 2) * 232 + sb] = kk.z;
                sk[(u * 4 + 3) * 232 + sb] = kk.w;
                sv[(u * 4 + 0) * 232 + sb] = vv.x;
                sv[(u * 4 + 1) * 232 + sb] = vv.y;
                sv[(u * 4 + 2) * 232 + sb] = vv.z;
                sv[(u * 4 + 3) * 232 + sb] = vv.w;
            }
        }
    }
    // ---- stage pooled k/v ----
    for (int idx = t; idx < 49 * 8; idx += 128) {
        int p = idx >> 3, d4 = idx & 7;
        const float4* src = (const float4*)(g_kvp + ((size_t)(b * PLP + p) * 512 + h * 32));
        *(float4*)(skp + p * 32 + d4 * 4) = src[d4];
        *(float4*)(svp + p * 32 + d4 * 4) = src[64 + d4];
    }
    // ---- stage learnable tokens ----
    for (int idx = t; idx < 288; idx += 128) {
        int d = idx / 9, l = idx - d * 9;
        sLT[l * 32 + d] = LT[(h * 32 + d) * 9 + l];
    }
    __syncthreads();

    // ---- per-lane compute ----
    const int i = i0 + (w >> 1);
    const int j = (w & 1) * 28 + lane;
    const bool act = lane < 28;
    const int n = i * 56 + j;

    float q[32];
    {
        const float4* qs = (const float4*)(g_q + (((size_t)b * 8 + h) * NTOK + (act ? n : i * 56)) * 32);
#pragma unroll
        for (int u = 0; u < 8; u++) {
            float4 qq = qs[u];
            q[u * 4 + 0] = qq.x; q[u * 4 + 1] = qq.y;
            q[u * 4 + 2] = qq.z; q[u * 4 + 3] = qq.w;
        }
    }

    // local logits
    float el[9];
    int slots[9];
#pragma unroll
    for (int l = 0; l < 9; l++) {
        int di = l / 3, dj = l - di * 3;
        int rslot = (w >> 1) + di;
        int cslot = j + dj;            // (j+dj-1)+1
        int slot = act ? (rslot * 58 + cslot) : 0;
        slots[l] = slot;
        float dot = 0.f;
#pragma unroll
        for (int d = 0; d < 32; d++) dot = fmaf(q[d], sk[d * 232 + slot], dot);
        bool valid = act && ((unsigned)(i + di - 1) < 56u) && ((unsigned)(j + dj - 1) < 56u);
        el[l] = valid ? (dot * ASCALE + __ldg(pbl + h * 9 + l)) : -1e30f;
    }
    // pooled logits
    float ep[49];
#pragma unroll 7
    for (int p = 0; p < 49; p++) {
        const float4* kp4 = (const float4*)(skp + p * 32);
        float dot = 0.f;
#pragma unroll
        for (int u = 0; u < 8; u++) {
            float4 kk = kp4[u];
            dot = fmaf(q[u * 4 + 0], kk.x, dot);
            dot = fmaf(q[u * 4 + 1], kk.y, dot);
            dot = fmaf(q[u * 4 + 2], kk.z, dot);
            dot = fmaf(q[u * 4 + 3], kk.w, dot);
        }
        ep[p] = dot * ASCALE + __ldg(pbp + h * 49 + p);
    }
    // learnable-token logits
    float A9[9];
#pragma unroll
    for (int l = 0; l < 9; l++) {
        const float4* lt4 = (const float4*)(sLT + l * 32);
        float dot = 0.f;
#pragma unroll
        for (int u = 0; u < 8; u++) {
            float4 kk = lt4[u];
            dot = fmaf(q[u * 4 + 0], kk.x, dot);
            dot = fmaf(q[u * 4 + 1], kk.y, dot);
            dot = fmaf(q[u * 4 + 2], kk.z, dot);
            dot = fmaf(q[u * 4 + 3], kk.w, dot);
        }
        A9[l] = dot + __ldg(lb + h * 9 + l);
    }

    // softmax over 58 (in registers, no communication)
    float mx = el[0];
#pragma unroll
    for (int l = 1; l < 9; l++) mx = fmaxf(mx, el[l]);
#pragma unroll
    for (int p = 0; p < 49; p++) mx = fmaxf(mx, ep[p]);
    float ssum = 0.f;
#pragma unroll
    for (int l = 0; l < 9; l++) { el[l] = __expf(el[l] - mx); ssum += el[l]; }
#pragma unroll
    for (int p = 0; p < 49; p++) { ep[p] = __expf(ep[p] - mx); ssum += ep[p]; }
    float inv = 1.f / ssum;
#pragma unroll
    for (int l = 0; l < 9; l++) A9[l] = fmaf(el[l], inv, A9[l]);
#pragma unroll
    for (int p = 0; p < 49; p++) ep[p] *= inv;

    // weighted sums (masked local slots hold zero v -> no branch needed)
    float o[32];
#pragma unroll
    for (int d = 0; d < 32; d++) o[d] = 0.f;
#pragma unroll
    for (int l = 0; l < 9; l++) {
        float wgt = A9[l];
        int slot = slots[l];
#pragma unroll
        for (int d = 0; d < 32; d++) o[d] = fmaf(wgt, sv[d * 232 + slot], o[d]);
    }
#pragma unroll 7
    for (int p = 0; p < 49; p++) {
        float wgt = ep[p];
        const float4* vp4 = (const float4*)(svp + p * 32);
#pragma unroll
        for (int u = 0; u < 8; u++) {
            float4 vv = vp4[u];
            o[u * 4 + 0] = fmaf(wgt, vv.x, o[u * 4 + 0]);
            o[u * 4 + 1] = fmaf(wgt, vv.y, o[u * 4 + 1]);
            o[u * 4 + 2] = fmaf(wgt, vv.z, o[u * 4 + 2]);
            o[u * 4 + 3] = fmaf(wgt, vv.w, o[u * 4 + 3]);
        }
    }

    if (act) {
        size_t base = ((size_t)b * NTOK + n) * 256 + h * 32;
        uint32_t* oh = (uint32_t*)(g_ohi + base);
        uint32_t* ol = (uint32_t*)(g_olo + base);
#pragma unroll
        for (int d2 = 0; d2 < 16; d2++) {
            float v0 = o[d2 * 2], v1 = o[d2 * 2 + 1];
            __nv_bfloat16 h0 = __float2bfloat16(v0);
            __nv_bfloat16 h1 = __float2bfloat16(v1);
            __nv_bfloat162 hi2 = __nv_bfloat162(h0, h1);
            __nv_bfloat162 lo2 = __nv_bfloat162(
                __float2bfloat16(v0 - __bfloat162float(h0)),
                __float2bfloat16(v1 - __bfloat162float(h1)));
            oh[d2] = *(uint32_t*)&hi2;
            ol[d2] = *(uint32_t*)&lo2;
        }
    }
}

// ---------------- launch -------------------------------------------------------
extern "C" void kernel_launch(void* const* d_in, const int* in_sizes, int n_in,
                              void* d_out, int out_size) {
    (void)in_sizes; (void)n_in; (void)out_size;
    const float* x     = (const float*)d_in[0];
    const float* Wq    = (const float*)d_in[1];
    const float* bq    = (const float*)d_in[2];
    const float* Wkv   = (const float*)d_in[3];
    const float* bkv   = (const float*)d_in[4];
    const float* qe    = (const float*)d_in[5];
    const float* Wsr   = (const float*)d_in[6];
    const float* bsr   = (const float*)d_in[7];
    const float* ln_g  = (const float*)d_in[8];
    const float* ln_b  = (const float*)d_in[9];
    const float* pbp   = (const float*)d_in[10];
    const float* pbl   = (const float*)d_in[11];
    const float* LT    = (const float*)d_in[12];
    const float* lb    = (const float*)d_in[13];
    const float* Wproj = (const float*)d_in[14];
    const float* bproj = (const float*)d_in[15];
    float* out = (float*)d_out;

    __nv_bfloat16 *pxhi, *pxlo, *pwthi, *pwtlo, *pwphi, *pwplo, *pohi, *polo;
    float* pbcat;
    cudaGetSymbolAddress((void**)&pxhi, g_xhi);
    cudaGetSymbolAddress((void**)&pxlo, g_xlo);
    cudaGetSymbolAddress((void**)&pwthi, g_wthi);
    cudaGetSymbolAddress((void**)&pwtlo, g_wtlo);
    cudaGetSymbolAddress((void**)&pwphi, g_wphi);
    cudaGetSymbolAddress((void**)&pwplo, g_wplo);
    cudaGetSymbolAddress((void**)&pohi, g_ohi);
    cudaGetSymbolAddress((void**)&polo, g_olo);
    cudaGetSymbolAddress((void**)&pbcat, g_bcat);

    cudaFuncSetAttribute(gemm_mma, cudaFuncAttributeMaxDynamicSharedMemorySize, 2 * SBUF);
    cudaFuncSetAttribute(attn2, cudaFuncAttributeMaxDynamicSharedMemorySize,
                         ATTN_SMEM_FLOATS * 4);

    pack_w<<<320, 256>>>(Wq, bq, Wkv, bkv, Wsr, bsr, qe, Wproj);
    split_x<<<2048, 256>>>(x);

    // fused q/kv/xsr GEMM: 25088 x 1024 x 256 (bf16x3 on HMMA)
    gemm_mma<<<dim3(8, 196), 256, 2 * SBUF>>>(pxhi, pxlo, pwthi, pwtlo, pbcat, nullptr, 0);

    pool_ln<<<BATCH * PLP, 256>>>(ln_g, ln_b);
    kvp_gemm<<<196, 256>>>(Wkv, bkv);

    attn2<<<dim3(28, 8, 8), 128, ATTN_SMEM_FLOATS * 4>>>(pbp, pbl, LT, lb);

    // projection GEMM: 25088 x 256 x 256 -> d_out
    gemm_mma<<<dim3(2, 196), 256, 2 * SBUF>>>(pohi, polo, pwphi, pwplo, bproj, out, 1);
}